// round 1
// baseline (speedup 1.0000x reference)
#include <cuda_runtime.h>

// Range_Fourier_Net: y = DFT_512(x) per row, complex, output stacked (re, im).
// Implemented as radix-8^3 FFT using exact twiddles read from the provided
// DFT weight matrix (row 1 = W512^m), so results match the fp32 reference
// to ~1e-6 while doing ~60x less math than the matmul formulation.
//
// Layout:
//   x_re, x_im : (32768, 512) float32
//   w_re, w_im : (512, 512) float32  (only row 1 used, as twiddle table)
//   out        : (32768, 512, 2) float32  -> float2 per (row, h)

#define ROWS_PER_CTA 4
#define CTA_THREADS (ROWS_PER_CTA * 64)
#define BUF_LEN 576   // 512 logical + 8 pad per 64-block

__device__ __forceinline__ float2 cadd(float2 a, float2 b) {
    return make_float2(a.x + b.x, a.y + b.y);
}
__device__ __forceinline__ float2 csub(float2 a, float2 b) {
    return make_float2(a.x - b.x, a.y - b.y);
}
__device__ __forceinline__ float2 cmul(float2 a, float2 b) {
    return make_float2(fmaf(a.x, b.x, -a.y * b.y), fmaf(a.x, b.y, a.y * b.x));
}
// multiply by -i  (W8^2)
__device__ __forceinline__ float2 mul_mi(float2 a) { return make_float2(a.y, -a.x); }

// Natural-order 8-point DFT: v[h] = sum_j v_in[j] * W8^{j*h}, W8 = exp(-i*pi/4)
__device__ __forceinline__ void dft8(float2 v[8]) {
    float2 e0 = v[0], e1 = v[2], e2 = v[4], e3 = v[6];
    float2 o0 = v[1], o1 = v[3], o2 = v[5], o3 = v[7];
    // DFT4 of evens
    float2 t0 = cadd(e0, e2), t1 = csub(e0, e2);
    float2 t2 = cadd(e1, e3), t3 = mul_mi(csub(e1, e3));
    float2 E0 = cadd(t0, t2), E2 = csub(t0, t2);
    float2 E1 = cadd(t1, t3), E3 = csub(t1, t3);
    // DFT4 of odds
    float2 s0 = cadd(o0, o2), s1 = csub(o0, o2);
    float2 s2 = cadd(o1, o3), s3 = mul_mi(csub(o1, o3));
    float2 O0 = cadd(s0, s2), O2 = csub(s0, s2);
    float2 O1 = cadd(s1, s3), O3 = csub(s1, s3);
    const float S = 0.70710678118654752440f;
    // O1 *= W8^1 = (S, -S); O2 *= W8^2 = -i; O3 *= W8^3 = (-S, -S)
    float2 W1 = make_float2(S * (O1.x + O1.y), S * (O1.y - O1.x));
    float2 W2 = mul_mi(O2);
    float2 W3 = make_float2(S * (O3.y - O3.x), -S * (O3.x + O3.y));
    v[0] = cadd(E0, O0); v[4] = csub(E0, O0);
    v[1] = cadd(E1, W1); v[5] = csub(E1, W1);
    v[2] = cadd(E2, W2); v[6] = csub(E2, W2);
    v[3] = cadd(E3, W3); v[7] = csub(E3, W3);
}

__device__ __forceinline__ int pad(int i) { return i + (i >> 6) * 8; }

__global__ __launch_bounds__(CTA_THREADS)
void fft512_kernel(const float* __restrict__ xre, const float* __restrict__ xim,
                   const float* __restrict__ wre, const float* __restrict__ wim,
                   float2* __restrict__ out, int nrows)
{
    __shared__ float twr[512], twi[512];
    __shared__ float bre[ROWS_PER_CTA][BUF_LEN];
    __shared__ float bim[ROWS_PER_CTA][BUF_LEN];

    const int tid = threadIdx.x;
    // Exact twiddles: W512^m = (w_re[1*512+m], w_im[1*512+m])
    for (int m = tid; m < 512; m += CTA_THREADS) {
        twr[m] = wre[512 + m];
        twi[m] = wim[512 + m];
    }

    const int grp = tid >> 6;      // row within CTA
    const int t   = tid & 63;      // 0..63: t = j1*8 + j0
    const long long row = (long long)blockIdx.x * ROWS_PER_CTA + grp;
    const bool active = row < (long long)nrows;

    // ---- Stage 1: radix-8 over j2 (stride 64), then twiddle W512^{t*h2} ----
    float2 v[8];
    if (active) {
        const float* xr = xre + row * 512;
        const float* xi = xim + row * 512;
        #pragma unroll
        for (int j2 = 0; j2 < 8; j2++)
            v[j2] = make_float2(xr[t + 64 * j2], xi[t + 64 * j2]);
    } else {
        #pragma unroll
        for (int j2 = 0; j2 < 8; j2++) v[j2] = make_float2(0.f, 0.f);
    }
    dft8(v);
    __syncthreads();   // twiddle table ready

    #pragma unroll
    for (int h2 = 1; h2 < 8; h2++) {
        int m = t * h2;                       // < 512
        v[h2] = cmul(v[h2], make_float2(twr[m], twi[m]));
    }
    #pragma unroll
    for (int h2 = 0; h2 < 8; h2++) {
        int p = pad(h2 * 64 + t);
        bre[grp][p] = v[h2].x;
        bim[grp][p] = v[h2].y;
    }
    __syncthreads();

    // ---- Stage 2: radix-8 over j1, twiddle W64^{j0*h1} = W512^{8*j0*h1} ----
    const int h2 = t >> 3, j0 = t & 7;
    float2 w[8];
    #pragma unroll
    for (int j1 = 0; j1 < 8; j1++) {
        int p = pad(h2 * 64 + j1 * 8 + j0);
        w[j1] = make_float2(bre[grp][p], bim[grp][p]);
    }
    dft8(w);
    #pragma unroll
    for (int h1 = 1; h1 < 8; h1++) {
        int m = 8 * j0 * h1;                  // < 512
        w[h1] = cmul(w[h1], make_float2(twr[m], twi[m]));
    }
    __syncthreads();   // all reads done before overwrite
    #pragma unroll
    for (int h1 = 0; h1 < 8; h1++) {
        int p = pad(j0 * 64 + h1 * 8 + h2);
        bre[grp][p] = w[h1].x;
        bim[grp][p] = w[h1].y;
    }
    __syncthreads();

    // ---- Stage 3: radix-8 over j0; output h = h0*64 + (h1*8 + h2) ----
    float2 z[8];
    #pragma unroll
    for (int j = 0; j < 8; j++) {
        int p = pad(j * 64 + t);              // t = h1*8 + h2 here
        z[j] = make_float2(bre[grp][p], bim[grp][p]);
    }
    dft8(z);

    if (active) {
        float2* orow = out + row * 512;
        #pragma unroll
        for (int h0 = 0; h0 < 8; h0++)
            orow[h0 * 64 + t] = z[h0];
    }
}

extern "C" void kernel_launch(void* const* d_in, const int* in_sizes, int n_in,
                              void* d_out, int out_size)
{
    const float* xre = (const float*)d_in[0];
    const float* xim = (const float*)d_in[1];
    const float* wre = (const float*)d_in[2];
    const float* wim = (const float*)d_in[3];
    float2* out = (float2*)d_out;

    const int nrows = in_sizes[0] / 512;      // 32768
    const int grid = (nrows + ROWS_PER_CTA - 1) / ROWS_PER_CTA;
    fft512_kernel<<<grid, CTA_THREADS>>>(xre, xim, wre, wim, out, nrows);
}

// round 2
// speedup vs baseline: 1.2581x; 1.2581x over previous
#include <cuda_runtime.h>

// Range_Fourier_Net: y = DFT_512(x) per row, complex, output stacked (re, im).
// Radix-8^3 FFT. Twiddles are generated in registers from per-thread base
// factors loaded (exactly) from row 1 of the provided DFT weight matrix —
// no shared twiddle table, no strided-conflict LDS.
//
// Shared exchanges:
//   exchange 1: pitch-72 blocked layout (conflict-free both directions)
//   exchange 2: pitch-68 layout  (banks 4*j0 + h2 + 8*h1 — a perfect cover)
// Row groups (64 threads) sync via named barriers, not CTA-wide syncthreads.

#define ROWS_PER_CTA 4
#define CTA_THREADS (ROWS_PER_CTA * 64)
#define BUF_LEN 576   // >= 7*72+63+1 and >= 7*68+63+1

__device__ __forceinline__ float2 cadd(float2 a, float2 b) {
    return make_float2(a.x + b.x, a.y + b.y);
}
__device__ __forceinline__ float2 csub(float2 a, float2 b) {
    return make_float2(a.x - b.x, a.y - b.y);
}
__device__ __forceinline__ float2 cmul(float2 a, float2 b) {
    return make_float2(fmaf(a.x, b.x, -a.y * b.y), fmaf(a.x, b.y, a.y * b.x));
}
// multiply by -i  (W8^2)
__device__ __forceinline__ float2 mul_mi(float2 a) { return make_float2(a.y, -a.x); }

// Natural-order 8-point DFT: v[h] = sum_j v_in[j] * W8^{j*h}, W8 = exp(-i*pi/4)
__device__ __forceinline__ void dft8(float2 v[8]) {
    float2 e0 = v[0], e1 = v[2], e2 = v[4], e3 = v[6];
    float2 o0 = v[1], o1 = v[3], o2 = v[5], o3 = v[7];
    float2 t0 = cadd(e0, e2), t1 = csub(e0, e2);
    float2 t2 = cadd(e1, e3), t3 = mul_mi(csub(e1, e3));
    float2 E0 = cadd(t0, t2), E2 = csub(t0, t2);
    float2 E1 = cadd(t1, t3), E3 = csub(t1, t3);
    float2 s0 = cadd(o0, o2), s1 = csub(o0, o2);
    float2 s2 = cadd(o1, o3), s3 = mul_mi(csub(o1, o3));
    float2 O0 = cadd(s0, s2), O2 = csub(s0, s2);
    float2 O1 = cadd(s1, s3), O3 = csub(s1, s3);
    const float S = 0.70710678118654752440f;
    float2 W1 = make_float2(S * (O1.x + O1.y), S * (O1.y - O1.x));
    float2 W2 = mul_mi(O2);
    float2 W3 = make_float2(S * (O3.y - O3.x), -S * (O3.x + O3.y));
    v[0] = cadd(E0, O0); v[4] = csub(E0, O0);
    v[1] = cadd(E1, W1); v[5] = csub(E1, W1);
    v[2] = cadd(E2, W2); v[6] = csub(E2, W2);
    v[3] = cadd(E3, W3); v[7] = csub(E3, W3);
}

__device__ __forceinline__ void group_bar(int grp) {
    asm volatile("bar.sync %0, 64;" :: "r"(grp + 1) : "memory");
}

__global__ __launch_bounds__(CTA_THREADS)
void fft512_kernel(const float* __restrict__ xre, const float* __restrict__ xim,
                   const float* __restrict__ wre, const float* __restrict__ wim,
                   float2* __restrict__ out, int nrows)
{
    __shared__ float bre[ROWS_PER_CTA][BUF_LEN];
    __shared__ float bim[ROWS_PER_CTA][BUF_LEN];

    const int tid = threadIdx.x;
    const int grp = tid >> 6;      // row within CTA
    const int t   = tid & 63;      // 0..63
    const int j0  = t & 7;
    const int h2s = t >> 3;        // "h2" role of this thread in stage 2
    const long long row = (long long)blockIdx.x * ROWS_PER_CTA + grp;
    const bool active = row < (long long)nrows;

    // Per-thread exact base twiddles from DFT-matrix row 1: W512^m = w[512+m]
    float2 base1 = make_float2(__ldg(&wre[512 + t]),      __ldg(&wim[512 + t]));       // W^t
    float2 base2 = make_float2(__ldg(&wre[512 + 8 * j0]), __ldg(&wim[512 + 8 * j0]));  // W^(8*j0)

    // ---- Stage 1: radix-8 over j2 (stride 64), twiddle (W^t)^h2 ----
    float2 v[8];
    if (active) {
        const float* xr = xre + row * 512;
        const float* xi = xim + row * 512;
        #pragma unroll
        for (int j2 = 0; j2 < 8; j2++)
            v[j2] = make_float2(xr[t + 64 * j2], xi[t + 64 * j2]);
    } else {
        #pragma unroll
        for (int j2 = 0; j2 < 8; j2++) v[j2] = make_float2(0.f, 0.f);
    }
    dft8(v);
    {
        float2 f = base1;
        #pragma unroll
        for (int h2 = 1; h2 < 8; h2++) {
            v[h2] = cmul(v[h2], f);
            if (h2 < 7) f = cmul(f, base1);
        }
    }
    // exchange 1 store: pitch 72 (conflict-free)
    #pragma unroll
    for (int h2 = 0; h2 < 8; h2++) {
        int p = h2 * 72 + t;
        bre[grp][p] = v[h2].x;
        bim[grp][p] = v[h2].y;
    }
    group_bar(grp);

    // ---- Stage 2: radix-8 over j1, twiddle (W^(8*j0))^h1 ----
    float2 w[8];
    #pragma unroll
    for (int j1 = 0; j1 < 8; j1++) {
        int p = h2s * 72 + j1 * 8 + j0;
        w[j1] = make_float2(bre[grp][p], bim[grp][p]);
    }
    dft8(w);
    {
        float2 f = base2;
        #pragma unroll
        for (int h1 = 1; h1 < 8; h1++) {
            w[h1] = cmul(w[h1], f);
            if (h1 < 7) f = cmul(f, base2);
        }
    }
    group_bar(grp);   // all exchange-1 reads done before overwrite
    // exchange 2 store: pitch 68 -> banks 4*j0 + h2 + 8*h1, perfect cover
    #pragma unroll
    for (int h1 = 0; h1 < 8; h1++) {
        int p = j0 * 68 + h1 * 8 + h2s;
        bre[grp][p] = w[h1].x;
        bim[grp][p] = w[h1].y;
    }
    group_bar(grp);

    // ---- Stage 3: radix-8 over j0; output h = h0*64 + t ----
    float2 z[8];
    #pragma unroll
    for (int j = 0; j < 8; j++) {
        int p = j * 68 + t;
        z[j] = make_float2(bre[grp][p], bim[grp][p]);
    }
    dft8(z);

    if (active) {
        float2* orow = out + row * 512;
        #pragma unroll
        for (int h0 = 0; h0 < 8; h0++)
            orow[h0 * 64 + t] = z[h0];
    }
}

extern "C" void kernel_launch(void* const* d_in, const int* in_sizes, int n_in,
                              void* d_out, int out_size)
{
    const float* xre = (const float*)d_in[0];
    const float* xim = (const float*)d_in[1];
    const float* wre = (const float*)d_in[2];
    const float* wim = (const float*)d_in[3];
    float2* out = (float2*)d_out;

    const int nrows = in_sizes[0] / 512;      // 32768
    const int grid = (nrows + ROWS_PER_CTA - 1) / ROWS_PER_CTA;
    fft512_kernel<<<grid, CTA_THREADS>>>(xre, xim, wre, wim, out, nrows);
}